// round 2
// baseline (speedup 1.0000x reference)
#include <cuda_runtime.h>
#include <math_constants.h>
#include <stdint.h>

// Problem constants
#define NROW   65536        // B*H*W = 64*32*32
#define KCODES 512
#define DDIM   64
#define QELEMS 4194304      // 64*64*32*32
#define ENC_ELEMS (NROW * KCODES)   // 33554432 floats = 128 MB
#define MAIN_BLOCKS 256
#define MAIN_THREADS 128
#define ROWS_PER_BLOCK 256  // 2 rows per thread

// Scratch (no cudaMalloc allowed)
__device__ int    g_idx[NROW];
__device__ double g_partial[MAIN_BLOCKS];
__device__ float  g_bn[KCODES];

// Shared memory layout: [weights 32768 f][bnorm 512 f][reduce 128 d]
#define SMEM_BYTES ((KCODES*DDIM + KCODES) * 4 + MAIN_THREADS * 8)

// ---------------------------------------------------------------------------
// Kernel 1: codebook squared norms, fp32 sequential (mimic reference rounding)
// ---------------------------------------------------------------------------
__global__ void wnorm_kernel(const float* __restrict__ w) {
    int k = blockIdx.x * blockDim.x + threadIdx.x;
    if (k < KCODES) {
        float acc = 0.0f;
        #pragma unroll
        for (int d = 0; d < DDIM; d++) {
            float v = w[k * DDIM + d];
            acc = __fadd_rn(acc, __fmul_rn(v, v));  // products rounded, then added
        }
        g_bn[k] = acc;
    }
}

// ---------------------------------------------------------------------------
// Kernel 2: main — per-row argmin over 512 codes + q_out + loss partials
// 2 rows per thread; codebook resident in shared memory.
// ---------------------------------------------------------------------------
__global__ void __launch_bounds__(MAIN_THREADS) vq_main(
    const float* __restrict__ x,
    const float* __restrict__ w,
    float* __restrict__ qout)
{
    extern __shared__ float sm[];
    float*  sw   = sm;                       // [512*64]
    float*  sb   = sm + KCODES * DDIM;       // [512]
    double* sred = (double*)(sb + KCODES);   // [128] (133120 % 8 == 0)

    const int tid = threadIdx.x;

    // Stage codebook + norms into smem (coalesced float4; w is harness-aligned)
    {
        const float4* w4  = (const float4*)w;
        float4*       sw4 = (float4*)sw;
        for (int i = tid; i < KCODES * DDIM / 4; i += MAIN_THREADS) sw4[i] = w4[i];
        for (int i = tid; i < KCODES; i += MAIN_THREADS) sb[i] = g_bn[i];
    }
    __syncthreads();

    const int n0 = blockIdx.x * ROWS_PER_BLOCK + tid;
    const int n1 = n0 + MAIN_THREADS;

    // x layout [B=64, D=64, H=32, W=32]; row n=(b*32+h)*32+w gathers stride-1024
    float xr0[DDIM], xr1[DDIM];
    {
        int b = n0 >> 10, hw = n0 & 1023;
        const float* p = x + (size_t)b * 65536 + hw;
        #pragma unroll
        for (int d = 0; d < DDIM; d++) xr0[d] = p[d * 1024];
    }
    {
        int b = n1 >> 10, hw = n1 & 1023;
        const float* p = x + (size_t)b * 65536 + hw;
        #pragma unroll
        for (int d = 0; d < DDIM; d++) xr1[d] = p[d * 1024];
    }

    // a = sum(x*x), fp32 sequential, products rounded separately (no FMA)
    float a0 = 0.0f, a1 = 0.0f;
    #pragma unroll
    for (int d = 0; d < DDIM; d++) {
        a0 = __fadd_rn(a0, __fmul_rn(xr0[d], xr0[d]));
        a1 = __fadd_rn(a1, __fmul_rn(xr1[d], xr1[d]));
    }

    float best0 = CUDART_INF_F, best1 = CUDART_INF_F;
    int   bi0 = 0, bi1 = 0;

    for (int k = 0; k < KCODES; k++) {
        const float4* wr = (const float4*)(sw + k * DDIM);
        float m0 = 0.0f, m1 = 0.0f;
        #pragma unroll
        for (int j = 0; j < DDIM / 4; j++) {
            float4 v = wr[j];
            m0 = __fmaf_rn(xr0[4*j + 0], v.x, m0);
            m0 = __fmaf_rn(xr0[4*j + 1], v.y, m0);
            m0 = __fmaf_rn(xr0[4*j + 2], v.z, m0);
            m0 = __fmaf_rn(xr0[4*j + 3], v.w, m0);
            m1 = __fmaf_rn(xr1[4*j + 0], v.x, m1);
            m1 = __fmaf_rn(xr1[4*j + 1], v.y, m1);
            m1 = __fmaf_rn(xr1[4*j + 2], v.z, m1);
            m1 = __fmaf_rn(xr1[4*j + 3], v.w, m1);
        }
        float bk = sb[k];
        // d = fl( fl(a + b) - fl(2*m) ) — exact reference rounding structure
        float d0 = __fsub_rn(__fadd_rn(a0, bk), __fmul_rn(2.0f, m0));
        float d1 = __fsub_rn(__fadd_rn(a1, bk), __fmul_rn(2.0f, m1));
        if (d0 < best0) { best0 = d0; bi0 = k; }  // strict < => first-index ties
        if (d1 < best1) { best1 = d1; bi1 = k; }
    }

    g_idx[n0] = bi0;
    g_idx[n1] = bi1;

    // q_out = fl(x + fl(q - x)) (straight-through, bit-replicated); loss terms.
    // qout base is d_out+4 bytes (NOT 16B aligned) -> scalar stores only.
    double ls = 0.0;
    {
        int b = n0 >> 10, hw = n0 & 1023;
        float* qp = qout + (size_t)b * 65536 + hw;
        const float* wq = sw + bi0 * DDIM;
        #pragma unroll
        for (int d = 0; d < DDIM; d++) {
            float diff = __fsub_rn(wq[d], xr0[d]);
            qp[d * 1024] = __fadd_rn(xr0[d], diff);
            ls += (double)__fmul_rn(diff, diff);
        }
    }
    {
        int b = n1 >> 10, hw = n1 & 1023;
        float* qp = qout + (size_t)b * 65536 + hw;
        const float* wq = sw + bi1 * DDIM;
        #pragma unroll
        for (int d = 0; d < DDIM; d++) {
            float diff = __fsub_rn(wq[d], xr1[d]);
            qp[d * 1024] = __fadd_rn(xr1[d], diff);
            ls += (double)__fmul_rn(diff, diff);
        }
    }

    sred[tid] = ls;
    __syncthreads();
    if (tid == 0) {
        double s = 0.0;
        for (int i = 0; i < MAIN_THREADS; i++) s += sred[i];  // deterministic order
        g_partial[blockIdx.x] = s;
    }
}

// ---------------------------------------------------------------------------
// Kernel 3: deterministic final loss = m + 0.25*m  (z_q == z_e numerically)
// ---------------------------------------------------------------------------
__global__ void loss_kernel(float* __restrict__ out) {
    double s = 0.0;
    for (int i = 0; i < MAIN_BLOCKS; i++) s += g_partial[i];
    float m = (float)(s / (double)QELEMS);
    out[0] = __fadd_rn(m, __fmul_rn(0.25f, m));
}

// ---------------------------------------------------------------------------
// Kernel 4a: zero-fill aligned interior of encodings with float4 stores.
// enc4 points to the first 16B-aligned address inside the region.
// ---------------------------------------------------------------------------
__global__ void enc_zero4(float4* __restrict__ enc4, int n4) {
    int i = blockIdx.x * blockDim.x + threadIdx.x;
    if (i < n4) enc4[i] = make_float4(0.f, 0.f, 0.f, 0.f);
}

// Kernel 4b: scalar head/tail zeros for the misaligned fringe.
__global__ void enc_fringe(float* __restrict__ enc, int nhead,
                           float* __restrict__ tail, int ntail) {
    int t = threadIdx.x;
    if (t < nhead) enc[t] = 0.0f;
    if (t >= 8 && t - 8 < ntail) tail[t - 8] = 0.0f;
}

// Kernel 4c: scatter the ones (after zero-fill; same-stream ordering).
__global__ void enc_scatter(float* __restrict__ enc) {
    int n = blockIdx.x * blockDim.x + threadIdx.x;
    if (n < NROW) enc[(size_t)n * KCODES + g_idx[n]] = 1.0f;
}

// ---------------------------------------------------------------------------
extern "C" void kernel_launch(void* const* d_in, const int* in_sizes, int n_in,
                              void* d_out, int out_size) {
    const float* x = (const float*)d_in[0];   // [64,64,32,32] fp32
    const float* w = (const float*)d_in[1];   // [512,64] fp32
    float* out  = (float*)d_out;
    float* loss = out;                        // [1]
    float* qout = out + 1;                    // [4194304] NCHW (4B-aligned only)
    float* enc  = out + 1 + QELEMS;           // [65536*512] (4B-aligned only)

    // Compute 16B-aligned interior of the encodings region (host-side ptr math).
    uintptr_t encAddr  = (uintptr_t)enc;
    uintptr_t aligned  = (encAddr + 15u) & ~(uintptr_t)15u;
    int   nhead = (int)((aligned - encAddr) >> 2);             // leading floats
    int   rem   = ENC_ELEMS - nhead;
    int   n4    = rem >> 2;                                    // float4 count
    int   ntail = rem & 3;                                     // trailing floats
    float4* enc4 = (float4*)aligned;
    float*  tail = (float*)aligned + ((size_t)n4 << 2);

    cudaFuncSetAttribute(vq_main, cudaFuncAttributeMaxDynamicSharedMemorySize,
                         SMEM_BYTES);

    wnorm_kernel<<<2, 256>>>(w);
    vq_main<<<MAIN_BLOCKS, MAIN_THREADS, SMEM_BYTES>>>(x, w, qout);
    loss_kernel<<<1, 1>>>(loss);
    enc_zero4<<<(n4 + 255) / 256, 256>>>(enc4, n4);
    enc_fringe<<<1, 32>>>(enc, nhead, tail, ntail);
    enc_scatter<<<NROW / 256, 256>>>(enc);
}